// round 2
// baseline (speedup 1.0000x reference)
#include <cuda_runtime.h>
#include <cstdint>

// ----------------------------------------------------------------------------
// RecursiveBlock: channel attention + CSWin attention, b=16, DIM=128, 64x64 fp32
// Channel attn expands to 256 channels (8 heads x 32); qkv has 768 rows.
// ----------------------------------------------------------------------------

typedef unsigned long long u64;

#define DEVFN __device__ __forceinline__

DEVFN u64 ffma2(u64 a, u64 b, u64 c) {
    u64 r; asm("fma.rn.f32x2 %0, %1, %2, %3;" : "=l"(r) : "l"(a), "l"(b), "l"(c)); return r;
}
DEVFN u64 fmul2(u64 a, u64 b) {
    u64 r; asm("mul.rn.f32x2 %0, %1, %2;" : "=l"(r) : "l"(a), "l"(b)); return r;
}
DEVFN u64 pack2(float lo, float hi) {
    u64 r; asm("mov.b64 %0, {%1, %2};" : "=l"(r) : "f"(lo), "f"(hi)); return r;
}
DEVFN float2 unpack2(u64 v) {
    float lo, hi; asm("mov.b64 {%0, %1}, %2;" : "=f"(lo), "=f"(hi) : "l"(v));
    return make_float2(lo, hi);
}

// Fast exp on the FMA pipe (avoids MUFU, rt=8/SMSP on B300). rel err ~6e-6.
DEVFN float fast_exp(float x) {
    float t = x * 1.4426950408889634f;
    t = fmaxf(t, -126.0f);
    float fi = floorf(t);
    float f = t - fi;
    float p = 1.5403530e-4f;
    p = fmaf(p, f, 1.3333558e-3f);
    p = fmaf(p, f, 9.6181291e-3f);
    p = fmaf(p, f, 5.5504109e-2f);
    p = fmaf(p, f, 2.4022651e-1f);
    p = fmaf(p, f, 6.9314718e-1f);
    p = fmaf(p, f, 1.0f);
    return p * __int_as_float(((int)fi + 127) << 23);
}

// ----------------------------------------------------------------------------
// Scratch buffers
// ----------------------------------------------------------------------------
#define NB 16
#define NSP 4096   // 64*64

__device__ float g_qkv [NB * 768 * NSP];   // channel-attn qkv (q:0-255, k:256-511, v:512-767)
__device__ float g_norm[NB * 8 * 64];      // inverse L2 norms per (b,h): q rows 0..31, k rows 32..63
__device__ float g_gram[NB * 8 * 32 * 32]; // raw Q.K^T
__device__ float g_catt[NB * 8 * 32 * 32]; // softmaxed channel attention
__device__ float g_M   [NB * 128 * 256];   // proj_w @ blockdiag(attn) fold
__device__ float g_x2  [NB * 128 * NSP];   // x + channel_attention(x)
__device__ float g_qk2 [NB * 256 * NSP];   // cswin qk
__device__ float g_vbuf[NB * 128 * NSP];   // cswin v
__device__ float g_lepe[NB * 64 * NSP];    // v_v lepe
__device__ float g_att [NB * 128 * NSP];   // cswin attention output (pre-proj)

// ----------------------------------------------------------------------------
// Generic batched SGEMM: C[b] = (Res?[b] +) A[b](M,K) @ B[b](K,N), N = 4096.
// 128x128 tile, BK=8, 256 threads, 8x8 micro-tile computed as f32x2 pairs.
// ----------------------------------------------------------------------------
template <int RESID>
__global__ void __launch_bounds__(256) sgemm_kernel(
    const float* __restrict__ A, const float* __restrict__ B,
    const float* __restrict__ R, float* __restrict__ C,
    int M, int K, long long sA, long long sB, long long sR, long long sC)
{
    const int N = 4096;
    int bz = blockIdx.z;
    A += bz * sA; B += bz * sB; C += bz * sC;
    if (RESID) R += bz * sR;

    int mBase = blockIdx.y * 128;
    int nBase = blockIdx.x * 128;

    __shared__ float As[8][128];
    __shared__ float Bs[8][128];

    int tid  = threadIdx.x;
    int aRow = tid >> 1;
    int aCol = (tid & 1) << 2;
    int bRow = tid >> 5;
    int bCol = (tid & 31) << 2;
    int tx = tid & 15, ty = tid >> 4;

    u64 acc[8][4];
#pragma unroll
    for (int i = 0; i < 8; i++)
#pragma unroll
        for (int j = 0; j < 4; j++) acc[i][j] = 0ull;

    const bool aValid = (mBase + aRow) < M;
    const float* Aptr = A + (long long)(mBase + aRow) * K + aCol;
    const float* Bptr = B + (long long)bRow * N + nBase + bCol;

    for (int k0 = 0; k0 < K; k0 += 8) {
        float4 av = make_float4(0.f, 0.f, 0.f, 0.f);
        if (aValid) av = *(const float4*)(Aptr + k0);
        float4 bv = *(const float4*)(Bptr + (long long)k0 * N);
        __syncthreads();
        As[aCol + 0][aRow] = av.x;
        As[aCol + 1][aRow] = av.y;
        As[aCol + 2][aRow] = av.z;
        As[aCol + 3][aRow] = av.w;
        *(float4*)&Bs[bRow][bCol] = bv;
        __syncthreads();
#pragma unroll
        for (int kk = 0; kk < 8; kk++) {
            float4 aLo = *(float4*)&As[kk][ty * 4];
            float4 aHi = *(float4*)&As[kk][64 + ty * 4];
            float4 bLo = *(float4*)&Bs[kk][tx * 4];
            float4 bHi = *(float4*)&Bs[kk][64 + tx * 4];
            u64 b2[4];
            b2[0] = pack2(bLo.x, bLo.y); b2[1] = pack2(bLo.z, bLo.w);
            b2[2] = pack2(bHi.x, bHi.y); b2[3] = pack2(bHi.z, bHi.w);
            float a[8] = {aLo.x, aLo.y, aLo.z, aLo.w, aHi.x, aHi.y, aHi.z, aHi.w};
#pragma unroll
            for (int i = 0; i < 8; i++) {
                u64 ad = pack2(a[i], a[i]);
#pragma unroll
                for (int j = 0; j < 4; j++) acc[i][j] = ffma2(ad, b2[j], acc[i][j]);
            }
        }
    }

#pragma unroll
    for (int i = 0; i < 8; i++) {
        int m = mBase + ((i < 4) ? (ty * 4 + i) : (64 + ty * 4 + (i - 4)));
        if (m < M) {
            long long rowoff = (long long)m * N + nBase;
#pragma unroll
            for (int half = 0; half < 2; half++) {
                int col = (half == 0) ? (tx * 4) : (64 + tx * 4);
                float2 p0 = unpack2(acc[i][half * 2 + 0]);
                float2 p1 = unpack2(acc[i][half * 2 + 1]);
                float4 v = make_float4(p0.x, p0.y, p1.x, p1.y);
                if (RESID) {
                    float4 rv = *(const float4*)&R[rowoff + col];
                    v.x += rv.x; v.y += rv.y; v.z += rv.z; v.w += rv.w;
                }
                *(float4*)&C[rowoff + col] = v;
            }
        }
    }
}

// ----------------------------------------------------------------------------
// Channel attention: inverse L2 norms of q/k rows (8192 rows of 4096)
// Row layout: bh = (b*8+h), r in [0,64): r<32 -> q row r, r>=32 -> k row r-32.
// q channel = h*32+r; k channel = 256 + h*32 + (r-32). Batch stride 768*NSP.
// ----------------------------------------------------------------------------
__global__ void __launch_bounds__(256) norm_kernel(const float* __restrict__ qkv,
                                                   float* __restrict__ norminv)
{
    int warp = threadIdx.x >> 5, lane = threadIdx.x & 31;
    int row = blockIdx.x * 8 + warp;          // 0..8191
    int bh = row >> 6;
    int r  = row & 63;
    int b = bh >> 3, h = bh & 7;
    int ch = (r < 32) ? (h * 32 + r) : (256 + h * 32 + (r - 32));
    const float* p = qkv + ((long long)b * 768 + ch) * NSP;
    float ss = 0.f;
    for (int i = lane; i < NSP; i += 32) { float v = p[i]; ss = fmaf(v, v, ss); }
#pragma unroll
    for (int off = 16; off > 0; off >>= 1) ss += __shfl_xor_sync(0xffffffffu, ss, off);
    if (lane == 0) norminv[row] = 1.0f / fmaxf(sqrtf(ss), 1e-12f);
}

// ----------------------------------------------------------------------------
// Gram: G[b][h] = Q(32,4096) @ K(32,4096)^T.  Block (16x16), 2x2 micro-tile.
// ----------------------------------------------------------------------------
__global__ void __launch_bounds__(256) gram_kernel(const float* __restrict__ qkv,
                                                   float* __restrict__ G)
{
    int bh = blockIdx.x;                       // 0..127
    int b = bh >> 3, h = bh & 7;
    const float* Q  = qkv + ((long long)b * 768 + h * 32) * NSP;
    const float* Kp = qkv + ((long long)b * 768 + 256 + h * 32) * NSP;

    __shared__ float Qs[32 * 68];
    __shared__ float Ks[32 * 68];

    int tx = threadIdx.x & 15, ty = threadIdx.x >> 4;
    float a00 = 0.f, a01 = 0.f, a10 = 0.f, a11 = 0.f;

    for (int c0 = 0; c0 < NSP; c0 += 64) {
        __syncthreads();
        for (int l = threadIdx.x; l < 2048; l += 256) {
            int r = l >> 6, cc = l & 63;
            Qs[r * 68 + cc] = Q[(long long)r * NSP + c0 + cc];
            Ks[r * 68 + cc] = Kp[(long long)r * NSP + c0 + cc];
        }
        __syncthreads();
#pragma unroll
        for (int tt = 0; tt < 64; tt += 4) {
            float4 q0 = *(float4*)&Qs[ty * 68 + tt];
            float4 q1 = *(float4*)&Qs[(ty + 16) * 68 + tt];
            float4 k0 = *(float4*)&Ks[tx * 68 + tt];
            float4 k1 = *(float4*)&Ks[(tx + 16) * 68 + tt];
            a00 = fmaf(q0.x, k0.x, fmaf(q0.y, k0.y, fmaf(q0.z, k0.z, fmaf(q0.w, k0.w, a00))));
            a01 = fmaf(q0.x, k1.x, fmaf(q0.y, k1.y, fmaf(q0.z, k1.z, fmaf(q0.w, k1.w, a01))));
            a10 = fmaf(q1.x, k0.x, fmaf(q1.y, k0.y, fmaf(q1.z, k0.z, fmaf(q1.w, k0.w, a10))));
            a11 = fmaf(q1.x, k1.x, fmaf(q1.y, k1.y, fmaf(q1.z, k1.z, fmaf(q1.w, k1.w, a11))));
        }
    }
    float* g = G + (long long)bh * 1024;
    g[ty * 32 + tx]              = a00;
    g[ty * 32 + tx + 16]         = a01;
    g[(ty + 16) * 32 + tx]       = a10;
    g[(ty + 16) * 32 + tx + 16]  = a11;
}

// ----------------------------------------------------------------------------
// Channel-attn softmax (32-wide rows)
// ----------------------------------------------------------------------------
__global__ void __launch_bounds__(1024) ca_softmax_kernel(
    const float* __restrict__ G, const float* __restrict__ norminv,
    const float* __restrict__ temp, float* __restrict__ attn)
{
    int bh = blockIdx.x;
    int h = bh & 7;
    int j = threadIdx.x & 31, i = threadIdx.x >> 5;
    float qi = norminv[bh * 64 + i];
    float kj = norminv[bh * 64 + 32 + j];
    float l = G[(long long)bh * 1024 + i * 32 + j] * qi * kj * temp[h];
    float m = l;
#pragma unroll
    for (int off = 16; off > 0; off >>= 1) m = fmaxf(m, __shfl_xor_sync(0xffffffffu, m, off));
    float p = fast_exp(l - m);
    float s = p;
#pragma unroll
    for (int off = 16; off > 0; off >>= 1) s += __shfl_xor_sync(0xffffffffu, s, off);
    attn[(long long)bh * 1024 + i * 32 + j] = p / s;
}

// ----------------------------------------------------------------------------
// Fold: M_b[o][h*32+j] = sum_i proj_w[o][h*32+i] * attn[b][h][i][j]
// proj_w is (128, 256) row-major.
// ----------------------------------------------------------------------------
__global__ void __launch_bounds__(256) fold_kernel(const float* __restrict__ attn,
                                                   const float* __restrict__ proj_w,
                                                   float* __restrict__ Mfold)
{
    int b = blockIdx.x;
    __shared__ float As[8192];
    for (int l = threadIdx.x; l < 8192; l += 256) As[l] = attn[(long long)b * 8192 + l];
    __syncthreads();
    for (int idx = threadIdx.x; idx < 32768; idx += 256) {
        int o = idx >> 8, c = idx & 255;
        int h = c >> 5, j = c & 31;
        const float* pw = proj_w + o * 256 + h * 32;
        const float* at = As + h * 1024 + j;
        float s = 0.f;
#pragma unroll
        for (int i = 0; i < 32; i++) s = fmaf(pw[i], at[i * 32], s);
        Mfold[(long long)b * 32768 + idx] = s;
    }
}

// ----------------------------------------------------------------------------
// CSWin window attention. One block per (window, head, batch), 256 tokens.
// DIR=0: horizontal (64x4 windows), DIR=1: vertical (4x64 windows).
// Single-pass softmax (scores are small; clamped at 60), fast_exp, f32x2 FMA.
// ----------------------------------------------------------------------------
template <int DIR>
__global__ void __launch_bounds__(256) cswin_kernel(
    const float* __restrict__ qk, const float* __restrict__ vbuf,
    const float* __restrict__ lepe, float* __restrict__ outp)
{
    int win = blockIdx.x, h = blockIdx.y, b = blockIdx.z;
    int t = threadIdx.x;

    long long qb = (long long)b * 256 * NSP;
    long long vb = (long long)b * 128 * NSP;
    int n;
    const float *qp, *kp, *vp, *lp;
    float* op;
    if (DIR == 0) {
        n  = ((t >> 2) << 6) + (win << 2) + (t & 3);
        qp = qk + qb + (long long)(h * 8) * NSP;
        kp = qk + qb + (long long)(128 + h * 8) * NSP;
        vp = vbuf + vb + (long long)(h * 8) * NSP;
        lp = vp;  // v_h_lepe = v_h
        op = outp + vb + (long long)(h * 8) * NSP;
    } else {
        n  = (((win << 2) + (t >> 6)) << 6) + (t & 63);
        qp = qk + qb + (long long)(64 + h * 8) * NSP;
        kp = qk + qb + (long long)(192 + h * 8) * NSP;
        vp = vbuf + vb + (long long)(64 + h * 8) * NSP;
        lp = lepe + (long long)b * 64 * NSP + (long long)(h * 8) * NSP;
        op = outp + vb + (long long)(64 + h * 8) * NSP;
    }

    __shared__ float4 Ks[256][2];
    __shared__ float4 Vs[256][2];

    float q[8], lep[8], kr[8], vr[8];
#pragma unroll
    for (int d = 0; d < 8; d++) {
        q[d]   = qp[d * NSP + n] * 0.25f;    // scale = (128/8)^-0.5
        kr[d]  = kp[d * NSP + n];
        vr[d]  = vp[d * NSP + n];
        lep[d] = lp[d * NSP + n];
    }
    Ks[t][0] = make_float4(kr[0], kr[1], kr[2], kr[3]);
    Ks[t][1] = make_float4(kr[4], kr[5], kr[6], kr[7]);
    Vs[t][0] = make_float4(vr[0], vr[1], vr[2], vr[3]);
    Vs[t][1] = make_float4(vr[4], vr[5], vr[6], vr[7]);

    u64 q2[4];
    q2[0] = pack2(q[0], q[1]); q2[1] = pack2(q[2], q[3]);
    q2[2] = pack2(q[4], q[5]); q2[3] = pack2(q[6], q[7]);
    __syncthreads();

    u64 acc[4] = {0ull, 0ull, 0ull, 0ull};
    float ssum = 0.f;
#pragma unroll 4
    for (int j = 0; j < 256; j++) {
        ulonglong2 ka = *(const ulonglong2*)&Ks[j][0];
        ulonglong2 kb = *(const ulonglong2*)&Ks[j][1];
        u64 s2 = fmul2(q2[0], ka.x);
        s2 = ffma2(q2[1], ka.y, s2);
        s2 = ffma2(q2[2], kb.x, s2);
        s2 = ffma2(q2[3], kb.y, s2);
        float2 sf = unpack2(s2);
        float sc = sf.x + sf.y;
        float p = fast_exp(fminf(sc, 60.f));
        ssum += p;
        u64 p2 = pack2(p, p);
        ulonglong2 va  = *(const ulonglong2*)&Vs[j][0];
        ulonglong2 vb2 = *(const ulonglong2*)&Vs[j][1];
        acc[0] = ffma2(p2, va.x,  acc[0]);
        acc[1] = ffma2(p2, va.y,  acc[1]);
        acc[2] = ffma2(p2, vb2.x, acc[2]);
        acc[3] = ffma2(p2, vb2.y, acc[3]);
    }

    float inv = 1.0f / ssum;
#pragma unroll
    for (int dp = 0; dp < 4; dp++) {
        float2 a = unpack2(acc[dp]);
        op[(dp * 2 + 0) * NSP + n] = fmaf(a.x, inv, lep[dp * 2 + 0]);
        op[(dp * 2 + 1) * NSP + n] = fmaf(a.y, inv, lep[dp * 2 + 1]);
    }
}

// ----------------------------------------------------------------------------
// Launch chain
// ----------------------------------------------------------------------------
extern "C" void kernel_launch(void* const* d_in, const int* in_sizes, int n_in,
                              void* d_out, int out_size)
{
    const float* x         = (const float*)d_in[0];
    const float* ca_temp   = (const float*)d_in[1];
    const float* ca_qkv_w  = (const float*)d_in[2];
    const float* ca_proj_w = (const float*)d_in[3];
    const float* cs_qk_w   = (const float*)d_in[4];
    const float* cs_v_w    = (const float*)d_in[5];
    const float* cs_vv_w   = (const float*)d_in[6];
    // d_in[7] = cs_vh_w (unused by reference)
    const float* cs_proj_w = (const float*)d_in[8];
    float* out = (float*)d_out;

    float *qkv, *nrm, *gram, *catt, *Mf, *x2, *qk2, *vbuf, *lep, *att;
    cudaGetSymbolAddress((void**)&qkv,  g_qkv);
    cudaGetSymbolAddress((void**)&nrm,  g_norm);
    cudaGetSymbolAddress((void**)&gram, g_gram);
    cudaGetSymbolAddress((void**)&catt, g_catt);
    cudaGetSymbolAddress((void**)&Mf,   g_M);
    cudaGetSymbolAddress((void**)&x2,   g_x2);
    cudaGetSymbolAddress((void**)&qk2,  g_qk2);
    cudaGetSymbolAddress((void**)&vbuf, g_vbuf);
    cudaGetSymbolAddress((void**)&lep,  g_lepe);
    cudaGetSymbolAddress((void**)&att,  g_att);

    const long long S128 = 128LL * NSP, S256 = 256LL * NSP, S768 = 768LL * NSP, S64 = 64LL * NSP;

    // 1. qkv = ca_qkv_w @ x            (M=768, K=128)
    sgemm_kernel<0><<<dim3(32, 6, NB), 256>>>(ca_qkv_w, x, nullptr, qkv,
                                              768, 128, 0, S128, 0, S768);
    // 2. q/k row inverse norms
    norm_kernel<<<1024, 256>>>(qkv, nrm);
    // 3. Gram matrices
    gram_kernel<<<128, 256>>>(qkv, gram);
    // 4. channel-attn softmax
    ca_softmax_kernel<<<128, 1024>>>(gram, nrm, ca_temp, catt);
    // 5. fold proj_w through attention
    fold_kernel<<<NB, 256>>>(catt, ca_proj_w, Mf);
    // 6. x2 = x + M_b @ V              (M=128, K=256; A per-batch, V = qkv[512:768])
    sgemm_kernel<1><<<dim3(32, 1, NB), 256>>>(Mf, qkv + 512 * NSP, x, x2,
                                              128, 256, 32768, S768, S128, S128);
    // 7. qk = cs_qk_w @ x2             (M=256, K=128)
    sgemm_kernel<0><<<dim3(32, 2, NB), 256>>>(cs_qk_w, x2, nullptr, qk2,
                                              256, 128, 0, S128, 0, S256);
    // 8. v = cs_v_w @ x2               (M=128, K=128)
    sgemm_kernel<0><<<dim3(32, 1, NB), 256>>>(cs_v_w, x2, nullptr, vbuf,
                                              128, 128, 0, S128, 0, S128);
    // 9. lepe_v = cs_vv_w @ v_v        (M=64, K=64)
    sgemm_kernel<0><<<dim3(32, 1, NB), 256>>>(cs_vv_w, vbuf + 64 * NSP, nullptr, lep,
                                              64, 64, 0, S128, 0, S64);
    // 10/11. CSWin attention, both directions
    cswin_kernel<0><<<dim3(16, 8, NB), 256>>>(qk2, vbuf, lep, att);
    cswin_kernel<1><<<dim3(16, 8, NB), 256>>>(qk2, vbuf, lep, att);
    // 12. out = x2 + cs_proj_w @ att   (M=128, K=128)
    sgemm_kernel<1><<<dim3(32, 1, NB), 256>>>(cs_proj_w, att, x2, out,
                                              128, 128, 0, S128, S128, S128);

    (void)in_sizes; (void)n_in; (void)out_size;
}